// round 15
// baseline (speedup 1.0000x reference)
#include <cuda_runtime.h>
#include <math_constants.h>

// Scratch + sync state (no dynamic allocation allowed).
__device__ float g_P4[2 * 256];          // maxpool16(x4)  [b, hw]
__device__ float g_T3[2 * 256 * 256];    // maxpool8(x3)   [b, j, hw]
__device__ int   g_done   = 0;           // prologue blocks completed
__device__ int   g_finish = 0;           // blocks completed (for replay reset)

#define N_PRO   1024                      // prologue blocks (half x3 plane each)
#define N_MAIN  4096                      // double-width main blocks
#define N_TOTAL (N_PRO + N_MAIN)

// ---------------------------------------------------------------------------
// Single fused kernel, grid = 5120 x 256.
//   bid [0, 1024): prologue: half of x3 plane p = bid>>1 (q = bid&1); blocks
//       0..511 also pool one x4 16x16 window -> P4. atomicAdd(g_done) at end.
//   bid [1024, 5120): DOUBLE main block: handles channel pair k0 = B&2047 and
//       k1 = k0+2048 of batch b = B>>11. k0 and k1 share the SAME T3 plane
//       (2048 % 256 == 0) and P4 batch -> T3/P4 L2 reads, the wait, and all
//       block overheads amortize over 2x the work; per-thread MLP doubles.
//       pre-wait: x2 pool4 (x2), x1 pool2 (x8), ff 4x LDG.128 (vector remap);
//       t0-only spin on g_done==N_PRO; post-wait: shmem-stage sums, 4x STG.128.
// Deadlock-free at any occupancy: prologue bids precede all main bids and
// prologue blocks never wait. Last finishing block resets counters (replays).
// ---------------------------------------------------------------------------
__global__ void __launch_bounds__(256) fused_all_kernel(
        const float* __restrict__ x1, const float* __restrict__ x2,
        const float* __restrict__ x3, const float* __restrict__ x4,
        const float* __restrict__ ff, float* __restrict__ out) {
    const int bid = blockIdx.x;
    const int t   = threadIdx.x;

    if (bid < N_PRO) {
        // ================= prologue block =================
        const bool hasP4 = (bid < 512);
        float xv = 0.0f;
        if (hasP4) {
            const int xb = bid >> 8, pix = bid & 255;
            xv = x4[(size_t)xb * 65536
                    + (16 * (pix >> 4) + (t >> 4)) * 256
                    + 16 * (pix & 15) + (t & 15)];
        }

        // ---- half of x3 plane p = bid>>1 : rows q*64..q*64+63 ----
        const int p   = bid >> 1;
        const int q   = bid & 1;
        const int sub = t & 1;
        const int o   = t >> 1;
        const int ohl = o >> 4;
        const int ow2 = o & 15;
        const float* base = x3 + (size_t)p * 16384;
        const int row0 = 8 * (q * 8 + ohl) + sub * 4;
        float m = -CUDART_INF_F;
#pragma unroll
        for (int r = 0; r < 4; ++r) {
            const float4* row = (const float4*)(base + (row0 + r) * 128 + 8 * ow2);
            float4 v0 = row[0];
            float4 v1 = row[1];
            m = fmaxf(m, fmaxf(fmaxf(v0.x, v0.y), fmaxf(v0.z, v0.w)));
            m = fmaxf(m, fmaxf(fmaxf(v1.x, v1.y), fmaxf(v1.z, v1.w)));
        }
        m = fmaxf(m, __shfl_xor_sync(0xFFFFFFFFu, m, 1));
        if (sub == 0)
            g_T3[(size_t)p * 256 + (q * 8 + ohl) * 16 + ow2] = m;

        if (hasP4) {
            __shared__ float red[8];
            float v = xv;
#pragma unroll
            for (int s = 16; s > 0; s >>= 1)
                v = fmaxf(v, __shfl_down_sync(0xFFFFFFFFu, v, s));
            if ((t & 31) == 0) red[t >> 5] = v;
            __syncthreads();
            if (t == 0) {
                float pm = red[0];
#pragma unroll
                for (int w = 1; w < 8; ++w) pm = fmaxf(pm, red[w]);
                g_P4[bid] = pm;
            }
        }

        __syncthreads();
        if (t == 0) {
            __threadfence();
            atomicAdd(&g_done, 1);
        }
    } else {
        // ================= double main block =================
        const int B  = bid - N_PRO;            // [0, 4096)
        const int b  = B >> 11;                 // batch
        const int k0 = B & 2047;                // first channel of the pair
        const int oh = t >> 4, ow = t & 15;
        const int mh = t >> 6, i4 = t & 63;     // ff/out vector remap

        float p2v[2], p1v[2][4];
        float4 fa[2], fb[2];
        size_t rowa[2];

#pragma unroll
        for (int u = 0; u < 2; ++u) {
            const int k = k0 + 2048 * u;

            // ---- x2 pool4 ----
            const float* x2p = x2 + ((size_t)b * 4096 + k) * 4096;
            float p2 = -CUDART_INF_F;
#pragma unroll
            for (int r = 0; r < 4; ++r) {
                float4 v = *(const float4*)(x2p + (4 * oh + r) * 64 + 4 * ow);
                p2 = fmaxf(p2, fmaxf(fmaxf(v.x, v.y), fmaxf(v.z, v.w)));
            }
            p2v[u] = p2;

            // ---- x1 pool2 (4 aliases) ----
#pragma unroll
            for (int m = 0; m < 4; ++m) {
                const int c = k + 4096 * m;
                const float* x1p = x1 + ((size_t)b * 16384 + c) * 1024;
                float2 a0 = *(const float2*)(x1p + (2 * oh)     * 32 + 2 * ow);
                float2 a1 = *(const float2*)(x1p + (2 * oh + 1) * 32 + 2 * ow);
                p1v[u][m] = fmaxf(fmaxf(a0.x, a0.y), fmaxf(a1.x, a1.y));
            }

            // ---- ff as 2x LDG.128 (plane mh, both tile halves) ----
            rowa[u] = ((size_t)b * 32768 + (k + 4096 * mh)) * 256 + 4 * i4;
            fa[u] = *(const float4*)(ff + rowa[u]);
            fb[u] = *(const float4*)(ff + rowa[u] + (size_t)16384 * 256);
        }

        // ---- wait for prologue: ONLY t==0 polls ----
        if (t == 0) {
            if (*(volatile int*)&g_done < N_PRO) {
                while (*(volatile int*)&g_done < N_PRO) __nanosleep(256);
            }
            __threadfence();                   // acquire side
        }
        __syncthreads();                       // block-wide release of the wait

        // T3/P4 loaded ONCE for the pair (same plane, same batch)
        const float tp = g_T3[((size_t)b * 256 + (k0 & 255)) * 256 + t]
                       + g_P4[b * 256 + t];

        // ---- stage per-pixel sums, then vectorized stores ----
        __shared__ float sh[2 * 4 * 256];
#pragma unroll
        for (int u = 0; u < 2; ++u) {
            const float basev = p2v[u] + tp;
#pragma unroll
            for (int m = 0; m < 4; ++m)
                sh[(u * 4 + m) * 256 + t] = basev + p1v[u][m];
        }
        __syncthreads();

#pragma unroll
        for (int u = 0; u < 2; ++u) {
            const float4 sv = *(const float4*)(sh + (u * 4 + mh) * 256 + 4 * i4);
            float4 ra, rb;
            ra.x = fmaxf(sv.x + fa[u].x, 0.0f);
            ra.y = fmaxf(sv.y + fa[u].y, 0.0f);
            ra.z = fmaxf(sv.z + fa[u].z, 0.0f);
            ra.w = fmaxf(sv.w + fa[u].w, 0.0f);
            rb.x = fmaxf(sv.x + fb[u].x, 0.0f);
            rb.y = fmaxf(sv.y + fb[u].y, 0.0f);
            rb.z = fmaxf(sv.z + fb[u].z, 0.0f);
            rb.w = fmaxf(sv.w + fb[u].w, 0.0f);
            *(float4*)(out + rowa[u]) = ra;
            *(float4*)(out + rowa[u] + (size_t)16384 * 256) = rb;
        }
    }

    // ---- replay-safe counter reset: last block of the grid cleans up ----
    __syncthreads();
    if (t == 0) {
        const int old = atomicAdd(&g_finish, 1);
        if (old == N_TOTAL - 1) {
            g_done   = 0;
            g_finish = 0;
            __threadfence();
        }
    }
}

// ---------------------------------------------------------------------------
// Launch: inputs in metadata order: x1, x2, x3, x4, pure_ff
// ---------------------------------------------------------------------------
extern "C" void kernel_launch(void* const* d_in, const int* in_sizes, int n_in,
                              void* d_out, int out_size) {
    const float* x1 = (const float*)d_in[0];
    const float* x2 = (const float*)d_in[1];
    const float* x3 = (const float*)d_in[2];
    const float* x4 = (const float*)d_in[3];
    const float* ff = (const float*)d_in[4];
    float* out = (float*)d_out;

    fused_all_kernel<<<N_TOTAL, 256>>>(x1, x2, x3, x4, ff, out);
}

// round 16
// speedup vs baseline: 1.0178x; 1.0178x over previous
#include <cuda_runtime.h>
#include <math_constants.h>

// Scratch + sync state (no dynamic allocation allowed).
__device__ float g_P4[2 * 256];          // maxpool16(x4)  [b, hw]
__device__ float g_T3[2 * 256 * 256];    // maxpool8(x3)   [b, j, hw]
__device__ int   g_done   = 0;           // prologue blocks completed
__device__ int   g_finish = 0;           // blocks completed (for replay reset)

#define N_PRO   1024                      // prologue blocks (half x3 plane each)
#define N_MAIN  8192                      // main blocks
#define N_TOTAL (N_PRO + N_MAIN)

// ---------------------------------------------------------------------------
// Single fused kernel, grid = 9216 x 256 (best-measured R14 skeleton +
// streaming hints on the no-reuse ff/out traffic).
//   bid [0, 1024): prologue: half of x3 plane p = bid>>1 (q = bid&1); blocks
//       0..511 also pool one x4 16x16 window -> P4. atomicAdd(g_done) at end.
//   bid [1024, 9216): main block (b, k):
//       pre-wait:  x2 pool4 (4x LDG.128), x1 pool2 (8x LDG.64), ff for BOTH
//                  tile halves of plane m=t>>6 as 2x LDG.128.CS,
//       t0-only spin on g_done==N_PRO,
//       post-wait: stage per-pixel sums in 4KB shmem, 2x STG.128.CS.
// Deadlock-free at any occupancy: prologue bids precede all main bids in the
// in-order dispatcher and prologue blocks never wait.
// ---------------------------------------------------------------------------
__global__ void __launch_bounds__(256) fused_all_kernel(
        const float* __restrict__ x1, const float* __restrict__ x2,
        const float* __restrict__ x3, const float* __restrict__ x4,
        const float* __restrict__ ff, float* __restrict__ out) {
    const int bid = blockIdx.x;
    const int t   = threadIdx.x;

    if (bid < N_PRO) {
        // ================= prologue block =================
        const bool hasP4 = (bid < 512);
        float xv = 0.0f;
        if (hasP4) {
            const int xb = bid >> 8, pix = bid & 255;
            xv = x4[(size_t)xb * 65536
                    + (16 * (pix >> 4) + (t >> 4)) * 256
                    + 16 * (pix & 15) + (t & 15)];
        }

        // ---- half of x3 plane p = bid>>1 : rows q*64..q*64+63 ----
        const int p   = bid >> 1;
        const int q   = bid & 1;
        const int sub = t & 1;
        const int o   = t >> 1;
        const int ohl = o >> 4;
        const int ow2 = o & 15;
        const float* base = x3 + (size_t)p * 16384;
        const int row0 = 8 * (q * 8 + ohl) + sub * 4;
        float m = -CUDART_INF_F;
#pragma unroll
        for (int r = 0; r < 4; ++r) {
            const float4* row = (const float4*)(base + (row0 + r) * 128 + 8 * ow2);
            float4 v0 = row[0];
            float4 v1 = row[1];
            m = fmaxf(m, fmaxf(fmaxf(v0.x, v0.y), fmaxf(v0.z, v0.w)));
            m = fmaxf(m, fmaxf(fmaxf(v1.x, v1.y), fmaxf(v1.z, v1.w)));
        }
        m = fmaxf(m, __shfl_xor_sync(0xFFFFFFFFu, m, 1));
        if (sub == 0)
            g_T3[(size_t)p * 256 + (q * 8 + ohl) * 16 + ow2] = m;

        if (hasP4) {
            __shared__ float red[8];
            float v = xv;
#pragma unroll
            for (int s = 16; s > 0; s >>= 1)
                v = fmaxf(v, __shfl_down_sync(0xFFFFFFFFu, v, s));
            if ((t & 31) == 0) red[t >> 5] = v;
            __syncthreads();
            if (t == 0) {
                float pm = red[0];
#pragma unroll
                for (int w = 1; w < 8; ++w) pm = fmaxf(pm, red[w]);
                g_P4[bid] = pm;
            }
        }

        __syncthreads();
        if (t == 0) {
            __threadfence();
            atomicAdd(&g_done, 1);
        }
    } else {
        // ================= main block =================
        const int B  = bid - N_PRO;            // [0, 8192)
        const int b  = B >> 12, k = B & 4095;
        const int oh = t >> 4, ow = t & 15;

        // ---- prologue-independent HBM reads: x2 pool4 (LDG.128) ----
        const float* x2p = x2 + ((size_t)b * 4096 + k) * 4096;
        float p2 = -CUDART_INF_F;
#pragma unroll
        for (int r = 0; r < 4; ++r) {
            float4 v = *(const float4*)(x2p + (4 * oh + r) * 64 + 4 * ow);
            p2 = fmaxf(p2, fmaxf(fmaxf(v.x, v.y), fmaxf(v.z, v.w)));
        }

        // ---- prologue-independent HBM reads: x1 pool2 (4 aliases) ----
        float p1v[4];
#pragma unroll
        for (int m = 0; m < 4; ++m) {
            const int c = k + 4096 * m;
            const float* x1p = x1 + ((size_t)b * 16384 + c) * 1024;
            float2 a0 = *(const float2*)(x1p + (2 * oh)     * 32 + 2 * ow);
            float2 a1 = *(const float2*)(x1p + (2 * oh + 1) * 32 + 2 * ow);
            p1v[m] = fmaxf(fmaxf(a0.x, a0.y), fmaxf(a1.x, a1.y));
        }

        // ---- ff as 2x LDG.128.CS (read-once, evict-first) ----
        const int mh = t >> 6, i4 = t & 63;
        const size_t rowa = ((size_t)b * 32768 + (k + 4096 * mh)) * 256 + 4 * i4;
        const size_t rowb = rowa + (size_t)16384 * 256;
        const float4 fa = __ldcs((const float4*)(ff + rowa));
        const float4 fb = __ldcs((const float4*)(ff + rowb));

        // ---- wait for prologue: ONLY t==0 polls ----
        if (t == 0) {
            if (*(volatile int*)&g_done < N_PRO) {
                while (*(volatile int*)&g_done < N_PRO) __nanosleep(256);
            }
            __threadfence();                   // acquire side
        }
        __syncthreads();                       // block-wide release of the wait

        const float basev = p2
                          + g_T3[((size_t)b * 256 + (k & 255)) * 256 + t]
                          + g_P4[b * 256 + t];

        // ---- stage per-pixel sums, then streaming vector stores ----
        __shared__ float sh[4 * 256];
#pragma unroll
        for (int m = 0; m < 4; ++m)
            sh[m * 256 + t] = basev + p1v[m];
        __syncthreads();

        const float4 sv = *(const float4*)(sh + mh * 256 + 4 * i4);
        float4 ra, rb;
        ra.x = fmaxf(sv.x + fa.x, 0.0f);
        ra.y = fmaxf(sv.y + fa.y, 0.0f);
        ra.z = fmaxf(sv.z + fa.z, 0.0f);
        ra.w = fmaxf(sv.w + fa.w, 0.0f);
        rb.x = fmaxf(sv.x + fb.x, 0.0f);
        rb.y = fmaxf(sv.y + fb.y, 0.0f);
        rb.z = fmaxf(sv.z + fb.z, 0.0f);
        rb.w = fmaxf(sv.w + fb.w, 0.0f);
        __stcs((float4*)(out + rowa), ra);
        __stcs((float4*)(out + rowb), rb);
    }

    // ---- replay-safe counter reset: last block of the grid cleans up ----
    __syncthreads();
    if (t == 0) {
        const int old = atomicAdd(&g_finish, 1);
        if (old == N_TOTAL - 1) {
            g_done   = 0;
            g_finish = 0;
            __threadfence();
        }
    }
}

// ---------------------------------------------------------------------------
// Launch: inputs in metadata order: x1, x2, x3, x4, pure_ff
// ---------------------------------------------------------------------------
extern "C" void kernel_launch(void* const* d_in, const int* in_sizes, int n_in,
                              void* d_out, int out_size) {
    const float* x1 = (const float*)d_in[0];
    const float* x2 = (const float*)d_in[1];
    const float* x3 = (const float*)d_in[2];
    const float* x4 = (const float*)d_in[3];
    const float* ff = (const float*)d_in[4];
    float* out = (float*)d_out;

    fused_all_kernel<<<N_TOTAL, 256>>>(x1, x2, x3, x4, ff, out);
}

// round 17
// speedup vs baseline: 1.0230x; 1.0052x over previous
#include <cuda_runtime.h>
#include <math_constants.h>

// Scratch + sync state (no dynamic allocation allowed).
__device__ float g_P4[2 * 256];          // maxpool16(x4)  [b, hw]
__device__ float g_T3[2 * 256 * 256];    // maxpool8(x3)   [b, j, hw]
__device__ int   g_done   = 0;           // prologue blocks completed
__device__ int   g_finish = 0;           // blocks completed (for replay reset)

#define N_PRO   1024                      // prologue blocks (half x3 plane each)
#define N_MAIN  8192                      // main blocks
#define N_TOTAL (N_PRO + N_MAIN)

// ---------------------------------------------------------------------------
// FINAL KERNEL (best-measured configuration, = R14):
// Single fused kernel, grid = 9216 x 256, all 436.7 MB moved once at ~6.7 TB/s.
//   bid [0, 1024): prologue: half of x3 plane p = bid>>1 (q = bid&1); blocks
//       0..511 also pool one x4 16x16 window -> P4. atomicAdd(g_done) at end.
//   bid [1024, 9216): main block (b, k):
//       pre-wait:  x2 pool4 (4x LDG.128), x1 pool2 (8x LDG.64), ff for BOTH
//                  tile halves of plane m=t>>6 as 2x LDG.128 (vector remap) —
//                  ALL prologue-independent reads in flight before the wait,
//       t0-only spin on g_done==N_PRO (no L2 spin-storm),
//       post-wait: stage per-pixel sums in 4KB shmem, 2x LDS.128 + 2x STG.128.
// Deadlock-free at any occupancy: prologue bids precede all main bids in the
// in-order dispatcher and prologue blocks never wait.
// Last finishing block resets counters so graph replays start clean.
// ---------------------------------------------------------------------------
__global__ void __launch_bounds__(256) fused_all_kernel(
        const float* __restrict__ x1, const float* __restrict__ x2,
        const float* __restrict__ x3, const float* __restrict__ x4,
        const float* __restrict__ ff, float* __restrict__ out) {
    const int bid = blockIdx.x;
    const int t   = threadIdx.x;

    if (bid < N_PRO) {
        // ================= prologue block =================
        const bool hasP4 = (bid < 512);
        float xv = 0.0f;
        if (hasP4) {
            const int xb = bid >> 8, pix = bid & 255;
            xv = x4[(size_t)xb * 65536
                    + (16 * (pix >> 4) + (t >> 4)) * 256
                    + 16 * (pix & 15) + (t & 15)];
        }

        // ---- half of x3 plane p = bid>>1 : rows q*64..q*64+63 ----
        const int p   = bid >> 1;
        const int q   = bid & 1;
        const int sub = t & 1;
        const int o   = t >> 1;
        const int ohl = o >> 4;
        const int ow2 = o & 15;
        const float* base = x3 + (size_t)p * 16384;
        const int row0 = 8 * (q * 8 + ohl) + sub * 4;
        float m = -CUDART_INF_F;
#pragma unroll
        for (int r = 0; r < 4; ++r) {
            const float4* row = (const float4*)(base + (row0 + r) * 128 + 8 * ow2);
            float4 v0 = row[0];
            float4 v1 = row[1];
            m = fmaxf(m, fmaxf(fmaxf(v0.x, v0.y), fmaxf(v0.z, v0.w)));
            m = fmaxf(m, fmaxf(fmaxf(v1.x, v1.y), fmaxf(v1.z, v1.w)));
        }
        m = fmaxf(m, __shfl_xor_sync(0xFFFFFFFFu, m, 1));
        if (sub == 0)
            g_T3[(size_t)p * 256 + (q * 8 + ohl) * 16 + ow2] = m;

        if (hasP4) {
            __shared__ float red[8];
            float v = xv;
#pragma unroll
            for (int s = 16; s > 0; s >>= 1)
                v = fmaxf(v, __shfl_down_sync(0xFFFFFFFFu, v, s));
            if ((t & 31) == 0) red[t >> 5] = v;
            __syncthreads();
            if (t == 0) {
                float pm = red[0];
#pragma unroll
                for (int w = 1; w < 8; ++w) pm = fmaxf(pm, red[w]);
                g_P4[bid] = pm;
            }
        }

        __syncthreads();
        if (t == 0) {
            __threadfence();
            atomicAdd(&g_done, 1);
        }
    } else {
        // ================= main block =================
        const int B  = bid - N_PRO;            // [0, 8192)
        const int b  = B >> 12, k = B & 4095;
        const int oh = t >> 4, ow = t & 15;

        // ---- prologue-independent HBM reads: x2 pool4 (LDG.128) ----
        const float* x2p = x2 + ((size_t)b * 4096 + k) * 4096;
        float p2 = -CUDART_INF_F;
#pragma unroll
        for (int r = 0; r < 4; ++r) {
            float4 v = *(const float4*)(x2p + (4 * oh + r) * 64 + 4 * ow);
            p2 = fmaxf(p2, fmaxf(fmaxf(v.x, v.y), fmaxf(v.z, v.w)));
        }

        // ---- prologue-independent HBM reads: x1 pool2 (4 aliases) ----
        float p1v[4];
#pragma unroll
        for (int m = 0; m < 4; ++m) {
            const int c = k + 4096 * m;
            const float* x1p = x1 + ((size_t)b * 16384 + c) * 1024;
            float2 a0 = *(const float2*)(x1p + (2 * oh)     * 32 + 2 * ow);
            float2 a1 = *(const float2*)(x1p + (2 * oh + 1) * 32 + 2 * ow);
            p1v[m] = fmaxf(fmaxf(a0.x, a0.y), fmaxf(a1.x, a1.y));
        }

        // ---- prologue-independent HBM reads: ff as 2x LDG.128 ----
        const int mh = t >> 6, i4 = t & 63;
        const size_t rowa = ((size_t)b * 32768 + (k + 4096 * mh)) * 256 + 4 * i4;
        const size_t rowb = rowa + (size_t)16384 * 256;
        const float4 fa = *(const float4*)(ff + rowa);
        const float4 fb = *(const float4*)(ff + rowb);

        // ---- wait for prologue: ONLY t==0 polls ----
        if (t == 0) {
            if (*(volatile int*)&g_done < N_PRO) {
                while (*(volatile int*)&g_done < N_PRO) __nanosleep(256);
            }
            __threadfence();                   // acquire side
        }
        __syncthreads();                       // block-wide release of the wait

        const float basev = p2
                          + g_T3[((size_t)b * 256 + (k & 255)) * 256 + t]
                          + g_P4[b * 256 + t];

        // ---- stage per-pixel sums, then vectorized stores ----
        __shared__ float sh[4 * 256];
#pragma unroll
        for (int m = 0; m < 4; ++m)
            sh[m * 256 + t] = basev + p1v[m];
        __syncthreads();

        const float4 sv = *(const float4*)(sh + mh * 256 + 4 * i4);
        float4 ra, rb;
        ra.x = fmaxf(sv.x + fa.x, 0.0f);
        ra.y = fmaxf(sv.y + fa.y, 0.0f);
        ra.z = fmaxf(sv.z + fa.z, 0.0f);
        ra.w = fmaxf(sv.w + fa.w, 0.0f);
        rb.x = fmaxf(sv.x + fb.x, 0.0f);
        rb.y = fmaxf(sv.y + fb.y, 0.0f);
        rb.z = fmaxf(sv.z + fb.z, 0.0f);
        rb.w = fmaxf(sv.w + fb.w, 0.0f);
        *(float4*)(out + rowa) = ra;
        *(float4*)(out + rowb) = rb;
    }

    // ---- replay-safe counter reset: last block of the grid cleans up ----
    __syncthreads();
    if (t == 0) {
        const int old = atomicAdd(&g_finish, 1);
        if (old == N_TOTAL - 1) {
            g_done   = 0;
            g_finish = 0;
            __threadfence();
        }
    }
}

// ---------------------------------------------------------------------------
// Launch: inputs in metadata order: x1, x2, x3, x4, pure_ff
// ---------------------------------------------------------------------------
extern "C" void kernel_launch(void* const* d_in, const int* in_sizes, int n_in,
                              void* d_out, int out_size) {
    const float* x1 = (const float*)d_in[0];
    const float* x2 = (const float*)d_in[1];
    const float* x3 = (const float*)d_in[2];
    const float* x4 = (const float*)d_in[3];
    const float* ff = (const float*)d_in[4];
    float* out = (float*)d_out;

    fused_all_kernel<<<N_TOTAL, 256>>>(x1, x2, x3, x4, ff, out);
}